// round 14
// baseline (speedup 1.0000x reference)
#include <cuda_runtime.h>
#include <math.h>

#define NB 8
#define NT 128
#define NU 64
#define NU1 65
#define NV 512
#define NEGF (-1e30f)

#define UT 5                      // u tiles (16 wide) covering 65
#define TT 8                      // t tiles
#define TILES_PER_B (UT * TT)     // 40
#define JOINT_CTAS (NB * TILES_PER_B)  // 320
#define TK 64                     // k-tile (8 iterations over NV=512)
#define NKI (NV / TK)             // 8
#define TSR (TK + 4)              // smem tile row stride (floats)

// dp staging: 64-row t-chunks, padded stride 66 (conflict-free diagonals)
#define CH 64
#define SST 66

// shared pool (union of joint / dp layouts; branches are CTA-exclusive)
//   dp:    sLPB[CH*SST] | sLPL[CH*SST] | bnd[16] | sFin[1]
//   joint: As0[16*TSR] | As1[16*TSR] | Bs0[16*TSR] | Bs1[16*TSR]  (17408 B)
#define POOL_FLOATS (2 * CH * SST + 24)   // 8472 floats = 33888 B

// ---------------- device scratch (no allocations allowed) ----------------
__device__ __align__(16) float g_lpb[NB * NT * NU1];  // log P(blank)  (b,t,u)
__device__ __align__(16) float g_lpl[NB * NT * NU];   // log P(label)  (b,t,u)
__device__ float g_cost[NB];
__device__ unsigned int g_rdy[NB * 2];   // [b][half]: tiles done (self-reset)
__device__ unsigned int g_done;          // dp CTAs done (self-reset)

__device__ __forceinline__ float lae(float a, float c) {
    float mx = fmaxf(a, c);
    float mn = fminf(a, c);
    return mx + __logf(1.0f + __expf(mn - mx));
}

__device__ __forceinline__ float4 exp4(float4 v) {
    float4 e;
    e.x = __expf(v.x); e.y = __expf(v.y);
    e.z = __expf(v.z); e.w = __expf(v.w);
    return e;
}

__global__ void __launch_bounds__(256)
rnnt_fused_kernel(const float* __restrict__ trans,
                  const float* __restrict__ pred,
                  const int* __restrict__ labels,
                  const int* __restrict__ act_lens,
                  const int* __restrict__ label_lens,
                  float* __restrict__ out) {
    __shared__ __align__(16) float pool[POOL_FLOATS];
    int tid = threadIdx.x;

    if (blockIdx.x < JOINT_CTAS) {
        // ==== JOINT: exp-GEMM, double-buffered k-loop, 1 barrier/iter =====
        // carve 4 tile buffers from the pool (each 16*TSR floats, 16B-aligned)
        float* AsBuf[2];
        float* BsBuf[2];
        AsBuf[0] = pool;
        AsBuf[1] = pool + 16 * TSR;
        BsBuf[0] = pool + 2 * 16 * TSR;
        BsBuf[1] = pool + 3 * 16 * TSR;

        int blk = blockIdx.x;
        int b   = blk / TILES_PER_B;
        int rem = blk - b * TILES_PER_B;
        int t0  = (rem / UT) * 16;
        int u0  = (rem % UT) * 16;

        const float* Tb = trans + ((size_t)(b * NT + t0)) * NV;
        const float* Pb = pred + ((size_t)b * NU1) * NV;

        int tx = tid & 15;     // u in tile
        int ty = tid >> 4;     // t in tile
        int sr = tid >> 4;     // staging row 0..15
        int sc = tid & 15;     // staging float4 col 0..15 (TK/4 = 16)

        const float* aSrc = Tb + (size_t)sr * NV + sc * 4;
        int uu = u0 + sr;
        const float* bSrc = (uu < NU1) ? (Pb + (size_t)uu * NV + sc * 4) : 0;

        // preload k-tile 0 -> buffer 0
        float4 ra = *(const float4*)(aSrc);
        float4 rb = bSrc ? *(const float4*)(bSrc) : make_float4(0.f, 0.f, 0.f, 0.f);
        ((float4*)(AsBuf[0] + sr * TSR))[sc] = exp4(ra);
        ((float4*)(BsBuf[0] + sr * TSR))[sc] =
            bSrc ? exp4(rb) : make_float4(0.f, 0.f, 0.f, 0.f);
        __syncthreads();

        float acc = 0.f;
        for (int i = 0; i < NKI; i++) {
            int cur = i & 1;
            // prefetch next k-tile while computing this one
            if (i + 1 < NKI) {
                ra = *(const float4*)(aSrc + (i + 1) * TK);
                if (bSrc) rb = *(const float4*)(bSrc + (i + 1) * TK);
            }
            const float4* a4 = (const float4*)(AsBuf[cur] + ty * TSR);
            const float4* b4 = (const float4*)(BsBuf[cur] + tx * TSR);
#pragma unroll
            for (int k = 0; k < TK / 4; k++) {
                float4 av = a4[k];
                float4 bv = b4[k];
                acc += av.x * bv.x + av.y * bv.y + av.z * bv.z + av.w * bv.w;
            }
            if (i + 1 < NKI) {
                // buffer cur^1 was last read at iter i-1 (fenced by that
                // iteration's barrier) -> safe to overwrite now
                ((float4*)(AsBuf[cur ^ 1] + sr * TSR))[sc] = exp4(ra);
                ((float4*)(BsBuf[cur ^ 1] + sr * TSR))[sc] =
                    bSrc ? exp4(rb) : make_float4(0.f, 0.f, 0.f, 0.f);
                __syncthreads();   // publish stores for iter i+1
            }
        }

        // epilogue: lse + gather blank/label logits
        int t = t0 + ty;
        int u = u0 + tx;
        if (u < NU1) {
            float lse = logf(acc);
            const float* trow = Tb + (size_t)ty * NV;
            const float* prow = Pb + (size_t)u * NV;
            g_lpb[(b * NT + t) * NU1 + u] = trow[0] + prow[0] - lse;
            if (u < NU) {
                int lab = labels[b * NU + u];
                g_lpl[(b * NT + t) * NU + u] = trow[lab] + prow[lab] - lse;
            }
        }
        __syncthreads();
        if (tid == 0) {
            __threadfence();                       // release lpb/lpl
            atomicAdd(&g_rdy[b * 2 + (t0 >= 64)], 1u);
        }
    } else {
        // ========== DP: 8-warp barrier wavefront (R12), per-half waits ====
        float* sLPB = pool;                     // CH*SST floats
        float* sLPL = pool + CH * SST;          // CH*SST floats
        float* bnd  = pool + 2 * CH * SST;      // [2][8] = 16 floats
        float* sFin = pool + 2 * CH * SST + 16; // 1 float

        int b = blockIdx.x - JOINT_CTAS;
        int lane = tid & 31;
        int w    = tid >> 5;
        int u    = tid;

        int te = act_lens[b] - 1;
        int ue = label_lens[b];

        float a = 0.f;   // rolling alpha register for this thread's u

        for (int chunk = 0; chunk < 2; chunk++) {
            // wait for this half's 20 tiles (chunk 1 also needs lpb row 63,
            // covered by chunk 0's wait). Grid is single-wave resident.
            if (tid == 0) {
                volatile unsigned int* p = &g_rdy[b * 2 + chunk];
                while (*p < 20u) __nanosleep(64);
                __threadfence();               // acquire lpb/lpl
            }
            __syncthreads();

            int t0c    = chunk * CH;
            int base_b = (chunk == 0) ? 0 : (t0c - 1);
            int base_l = t0c;

            // stage tables (L2-coherent loads; writers are other SMs)
            {
                const float* gB = g_lpb + ((size_t)(b * NT + base_b)) * NU1;
                for (int i = tid; i < CH * NU1; i += 256) {
                    int r = i / NU1, c = i - r * NU1;
                    sLPB[r * SST + c] = __ldcg(gB + i);
                }
                const float* gL = g_lpl + ((size_t)(b * NT + base_l)) * NU;
                for (int i = tid; i < CH * NU; i += 256) {
                    sLPL[(i >> 6) * SST + (i & 63)] = __ldcg(gL + i);
                }
            }
            __syncthreads();

            int dl_lo = (chunk == 0) ? 1 : 0;   // (0,0) seeded a=0
            for (int dl = dl_lo; dl <= CH - 1 + NU1 - 1; dl++) {
                int p = dl & 1;
                float up = __shfl_up_sync(0xffffffffu, a, 1);
                if (lane == 0 && w > 0) up = bnd[(p ^ 1) * 8 + (w - 1)];

                int t = t0c + dl - u;
                if (u < NU1 && t >= t0c && t <= t0c + CH - 1) {
                    float pa = (t >= 1)
                        ? a + sLPB[(t - 1 - base_b) * SST + u] : NEGF;
                    float pb = (u >= 1)
                        ? up + sLPL[(t - base_l) * SST + (u - 1)] : NEGF;
                    a = lae(pa, pb);
                    if (t == te && u == ue) *sFin = a;
                }
                if (lane == 31) bnd[p * 8 + w] = a;
                __syncthreads();
            }
        }

        if (tid == 0) {
            float lpb_fin = __ldcg(&g_lpb[(size_t)(b * NT + te) * NU1 + ue]);
            g_cost[b] = -(*sFin + lpb_fin);
            __threadfence();
            unsigned int prev = atomicAdd(&g_done, 1u);
            if (prev == NB - 1) {   // last dp CTA: fixed-order deterministic sum
                float s = 0.f;
                volatile float* vc = g_cost;
                for (int i = 0; i < NB; i++) s += vc[i];
                out[0] = s;
                g_done = 0;          // self-reset for next replay
            }
            g_rdy[b * 2] = 0;        // self-reset (all arrivals observed)
            g_rdy[b * 2 + 1] = 0;
        }
    }
}

extern "C" void kernel_launch(void* const* d_in, const int* in_sizes, int n_in,
                              void* d_out, int out_size) {
    const float* trans   = (const float*)d_in[0];  // (B,T,V)
    const float* pred    = (const float*)d_in[1];  // (B,U1,V)
    const int*   labels  = (const int*)d_in[2];    // (B,U)
    const int*   act_l   = (const int*)d_in[3];    // (B,)
    const int*   label_l = (const int*)d_in[4];    // (B,)
    float*       out     = (float*)d_out;

    rnnt_fused_kernel<<<JOINT_CTAS + NB, 256>>>(trans, pred, labels,
                                                act_l, label_l, out);
}